// round 5
// baseline (speedup 1.0000x reference)
#include <cuda_runtime.h>

// GIoU loss mean over N=4,000,000 box pairs. Single fused kernel.
// Loop body slimmed to ONE fast division:
//   1 - giou = 2 - (inter*area_c + union^2) / (union*area_c)
// mean(1-giou) = 2 - sum(ratio)/N  -> constant folded out of the loop.

#define NBLOCKS 1184   // one full wave: 148 SMs x 8 CTAs
#define NTHREADS 256

__device__ float g_partials[NBLOCKS];
__device__ unsigned int g_count;   // zero at load; last block resets -> replay-safe

__global__ __launch_bounds__(NTHREADS)
void giou_fused_kernel(const float4* __restrict__ pred,
                       const float4* __restrict__ tgt,
                       float* __restrict__ out,
                       int n, float inv_n) {
    const int stride = gridDim.x * blockDim.x;
    const int tid0 = blockIdx.x * blockDim.x + threadIdx.x;

    const float4* __restrict__ pp = pred + tid0;
    const float4* __restrict__ tp = tgt + tid0;

    float acc = 0.0f;

    for (int i = tid0; i < n; i += stride, pp += stride, tp += stride) {
        float4 p = __ldg(pp);   // (x1, y1, x2, y2)
        float4 t = __ldg(tp);

        float area_p = (p.z - p.x) * (p.w - p.y);
        float area_t = (t.z - t.x) * (t.w - t.y);

        float iw = fmaxf(fminf(p.z, t.z) - fmaxf(p.x, t.x), 0.0f);
        float ih = fmaxf(fminf(p.w, t.w) - fmaxf(p.y, t.y), 0.0f);
        float inter = iw * ih;
        float uni   = area_p + area_t - inter;

        float cw = fmaxf(p.z, t.z) - fminf(p.x, t.x);
        float ch = fmaxf(p.w, t.w) - fminf(p.y, t.y);
        float area_c = cw * ch;

        // iou + union/area_c = (inter*area_c + union^2) / (union*area_c)
        float num = fmaf(uni, uni, inter * area_c);
        float den = uni * area_c;
        acc += __fdividef(num, den);
    }

    // Intra-block reduction (fixed order -> deterministic)
    #pragma unroll
    for (int o = 16; o > 0; o >>= 1)
        acc += __shfl_xor_sync(0xffffffffu, acc, o);

    __shared__ float s[NTHREADS / 32];
    if ((threadIdx.x & 31) == 0) s[threadIdx.x >> 5] = acc;
    __syncthreads();

    __shared__ bool is_last;
    if (threadIdx.x == 0) {
        float v = 0.0f;
        #pragma unroll
        for (int w = 0; w < NTHREADS / 32; w++) v += s[w];
        g_partials[blockIdx.x] = v;
        __threadfence();
        unsigned int prev = atomicAdd(&g_count, 1u);
        is_last = (prev == (unsigned int)(gridDim.x - 1));
    }
    __syncthreads();

    if (!is_last) return;

    // Last block: reduce all 1184 partials (L2-hot), deterministic order.
    float v = 0.0f;
    for (int b = threadIdx.x; b < NBLOCKS; b += NTHREADS)
        v += g_partials[b];

    #pragma unroll
    for (int o = 16; o > 0; o >>= 1)
        v += __shfl_xor_sync(0xffffffffu, v, o);

    __shared__ float s2[NTHREADS / 32];
    if ((threadIdx.x & 31) == 0) s2[threadIdx.x >> 5] = v;
    __syncthreads();

    if (threadIdx.x == 0) {
        float r = 0.0f;
        #pragma unroll
        for (int w = 0; w < NTHREADS / 32; w++) r += s2[w];
        *out = 2.0f - r * inv_n;   // mean(1 - giou)
        g_count = 0;               // reset for next replay
    }
}

extern "C" void kernel_launch(void* const* d_in, const int* in_sizes, int n_in,
                              void* d_out, int out_size) {
    const float4* pred = (const float4*)d_in[0];
    const float4* tgt  = (const float4*)d_in[1];
    float* out = (float*)d_out;

    const int n = in_sizes[0] / 4;   // floats -> boxes

    giou_fused_kernel<<<NBLOCKS, NTHREADS>>>(pred, tgt, out, n, 1.0f / (float)n);
}

// round 6
// speedup vs baseline: 1.0730x; 1.0730x over previous
#include <cuda_runtime.h>

// GIoU loss mean over N=4,000,000 box pairs. Single fused kernel.
// Unroll x2 over grid stride: 4 fully-coalesced LDG.128 front-batched
// (MLP_p1=4) with launch_bounds capping regs so occupancy stays >= 75%.
// Streaming loads (__ldcs): zero reuse, evict-first.

#define NBLOCKS 1184   // one full wave: 148 SMs x 8 CTAs
#define NTHREADS 256

__device__ float g_partials[NBLOCKS];
__device__ unsigned int g_count;   // zero at load; last block resets -> replay-safe

__device__ __forceinline__ float giou_term(float4 p, float4 t) {
    float area_p = (p.z - p.x) * (p.w - p.y);
    float area_t = (t.z - t.x) * (t.w - t.y);

    float iw = fmaxf(fminf(p.z, t.z) - fmaxf(p.x, t.x), 0.0f);
    float ih = fmaxf(fminf(p.w, t.w) - fmaxf(p.y, t.y), 0.0f);
    float inter = iw * ih;
    float uni   = area_p + area_t - inter;

    float cw = fmaxf(p.z, t.z) - fminf(p.x, t.x);
    float ch = fmaxf(p.w, t.w) - fminf(p.y, t.y);
    float area_c = cw * ch;

    // iou + union/area_c  (caller folds "2 -" out of the loop)
    float num = fmaf(uni, uni, inter * area_c);
    float den = uni * area_c;
    return __fdividef(num, den);
}

__global__ __launch_bounds__(NTHREADS, 6)
void giou_fused_kernel(const float4* __restrict__ pred,
                       const float4* __restrict__ tgt,
                       float* __restrict__ out,
                       int n, float inv_n) {
    const int stride = gridDim.x * blockDim.x;
    int i = blockIdx.x * blockDim.x + threadIdx.x;

    float acc = 0.0f;

    // Unroll x2: 4 independent coalesced LDG.128 in flight per iteration.
    for (; i + stride < n; i += 2 * stride) {
        float4 p0 = __ldcs(&pred[i]);
        float4 t0 = __ldcs(&tgt[i]);
        float4 p1 = __ldcs(&pred[i + stride]);
        float4 t1 = __ldcs(&tgt[i + stride]);
        acc += giou_term(p0, t0);   // frees p0/t0 while p1/t1 still in flight
        acc += giou_term(p1, t1);
    }
    if (i < n)
        acc += giou_term(__ldcs(&pred[i]), __ldcs(&tgt[i]));

    // Intra-block reduction (fixed order -> deterministic)
    #pragma unroll
    for (int o = 16; o > 0; o >>= 1)
        acc += __shfl_xor_sync(0xffffffffu, acc, o);

    __shared__ float s[NTHREADS / 32];
    if ((threadIdx.x & 31) == 0) s[threadIdx.x >> 5] = acc;
    __syncthreads();

    __shared__ bool is_last;
    if (threadIdx.x == 0) {
        float v = 0.0f;
        #pragma unroll
        for (int w = 0; w < NTHREADS / 32; w++) v += s[w];
        g_partials[blockIdx.x] = v;
        __threadfence();
        unsigned int prev = atomicAdd(&g_count, 1u);
        is_last = (prev == (unsigned int)(gridDim.x - 1));
    }
    __syncthreads();

    if (!is_last) return;

    // Last block: reduce all 1184 partials (L2-hot), deterministic order.
    float v = 0.0f;
    for (int b = threadIdx.x; b < NBLOCKS; b += NTHREADS)
        v += g_partials[b];

    #pragma unroll
    for (int o = 16; o > 0; o >>= 1)
        v += __shfl_xor_sync(0xffffffffu, v, o);

    __shared__ float s2[NTHREADS / 32];
    if ((threadIdx.x & 31) == 0) s2[threadIdx.x >> 5] = v;
    __syncthreads();

    if (threadIdx.x == 0) {
        float r = 0.0f;
        #pragma unroll
        for (int w = 0; w < NTHREADS / 32; w++) r += s2[w];
        *out = 2.0f - r * inv_n;   // mean(1 - giou)
        g_count = 0;               // reset for next replay
    }
}

extern "C" void kernel_launch(void* const* d_in, const int* in_sizes, int n_in,
                              void* d_out, int out_size) {
    const float4* pred = (const float4*)d_in[0];
    const float4* tgt  = (const float4*)d_in[1];
    float* out = (float*)d_out;

    const int n = in_sizes[0] / 4;   // floats -> boxes

    giou_fused_kernel<<<NBLOCKS, NTHREADS>>>(pred, tgt, out, n, 1.0f / (float)n);
}